// round 6
// baseline (speedup 1.0000x reference)
#include <cuda_runtime.h>
#include <math.h>
#include <stdint.h>

// ---------------------------------------------------------------------------
// Scratch (__device__ globals; no allocation allowed)
// ---------------------------------------------------------------------------
__device__ float g_pos[32 * 1024];              // [32 ch][1024], fp32
__device__ float g_x0[32 * 160 * 1024];         // tf32 [B][160][N]  (x|pos)
__device__ float g_kc[32 * 128 * 1024];         // tf32 k
__device__ float g_vc[32 * 128 * 1024];         // tf32 v
__device__ float g_q [32 * 128 * 1024];         // tf32 q
__device__ float g_Wq [128 * 160];              // tf32 weights
__device__ float g_Wfk[128 * 288];
__device__ float g_Wck[128 * 288];
__device__ float g_Wfv[128 * 288];
__device__ float g_Wcv[128 * 288];

// ---------------------------------------------------------------------------
// Helpers
// ---------------------------------------------------------------------------
__device__ __forceinline__ uint32_t f2tf(float x) {
    uint32_t u;
    asm("cvt.rna.tf32.f32 %0, %1;" : "=r"(u) : "f"(x));
    return u;
}
__device__ __forceinline__ float f2tff(float x) { return __uint_as_float(f2tf(x)); }

__device__ __forceinline__ void mma_tf32(
    float& d0, float& d1, float& d2, float& d3,
    uint32_t a0, uint32_t a1, uint32_t a2, uint32_t a3,
    uint32_t b0, uint32_t b1)
{
    asm volatile(
        "mma.sync.aligned.m16n8k8.row.col.f32.tf32.tf32.f32 "
        "{%0,%1,%2,%3}, {%4,%5,%6,%7}, {%8,%9}, {%0,%1,%2,%3};"
        : "+f"(d0), "+f"(d1), "+f"(d2), "+f"(d3)
        : "r"(a0), "r"(a1), "r"(a2), "r"(a3), "r"(b0), "r"(b1));
}

__device__ __forceinline__ void cpa16(uint32_t dst, const void* src) {
    asm volatile("cp.async.ca.shared.global [%0], [%1], 16;" :: "r"(dst), "l"(src));
}
#define CP_COMMIT() asm volatile("cp.async.commit_group;" ::: "memory")

// ---------------------------------------------------------------------------
// Positional embedding (faithful to numpy .view reinterpret)
// ---------------------------------------------------------------------------
__global__ void pos_kernel() {
    int idx = blockIdx.x * blockDim.x + threadIdx.x;
    if (idx >= 32 * 1024) return;
    int c = idx >> 10, n = idx & 1023;
    int y = n >> 5, x = n & 31;
    int i = (c < 16) ? (c * 32 + y) : ((c - 16) * 32 + x);
    int p = i >> 4, j = i & 15;
    float r = 0.0f;
    if (p != 0) {
        double denom = pow(10000.0, (double)(2 * (j >> 1)) / 16.0);
        double val = (double)p / denom;
        r = (j & 1) ? (float)cos(val) : (float)sin(val);
    }
    g_pos[idx] = r;
}

// ---------------------------------------------------------------------------
// Pack: tf32-round inputs AND weights into scratch (one launch)
// ---------------------------------------------------------------------------
__device__ __forceinline__ float4 tf4(float4 s) {
    s.x = f2tff(s.x); s.y = f2tff(s.y); s.z = f2tff(s.z); s.w = f2tff(s.w);
    return s;
}

#define PACK_NX0 (32 * 160 * 256)
#define PACK_NKV (32 * 128 * 256)
#define PACK_DATA (PACK_NX0 + 2 * PACK_NKV)
#define PACK_TOTAL (PACK_DATA + 128 * 288)

__global__ void pack_kernel(const float* __restrict__ x,
                            const float* __restrict__ k,
                            const float* __restrict__ v,
                            const float* __restrict__ Wq,
                            const float* __restrict__ Wfk, const float* __restrict__ Wck,
                            const float* __restrict__ Wfv, const float* __restrict__ Wcv)
{
    int i = blockIdx.x * blockDim.x + threadIdx.x;
    if (i < PACK_NX0) {
        int n4 = i & 255;
        int cb = i >> 8;
        int c = cb % 160, b = cb / 160;
        float4 s;
        if (c < 128)
            s = ((const float4*)x)[(size_t)(b * 128 + c) * 256 + n4];
        else
            s = ((const float4*)g_pos)[(c - 128) * 256 + n4];
        ((float4*)g_x0)[i] = tf4(s);
    } else if (i < PACK_NX0 + PACK_NKV) {
        int j = i - PACK_NX0;
        ((float4*)g_kc)[j] = tf4(((const float4*)k)[j]);
    } else if (i < PACK_DATA) {
        int j = i - PACK_NX0 - PACK_NKV;
        ((float4*)g_vc)[j] = tf4(((const float4*)v)[j]);
    } else {
        int j = i - PACK_DATA;                 // 0 .. 128*288-1
        if (j < 128 * 160) g_Wq[j] = f2tff(Wq[j]);
        g_Wfk[j] = f2tff(Wfk[j]);
        g_Wck[j] = f2tff(Wck[j]);
        g_Wfv[j] = f2tff(Wfv[j]);
        g_Wcv[j] = f2tff(Wcv[j]);
    }
}

// ---------------------------------------------------------------------------
// Fused GEMM kernel:
//   z in [0,64)  : gated highway update (z = b*2 + which), K=288, 9 steps
//   z in [64,96) : q = tf32(relu(Wq@x0+bq)) for b = z-64, K=160, 5 steps
// Both: CTA 64 out-rows x 128 cols, cp.async double-buffered, 8 warps.
// ---------------------------------------------------------------------------
#define GSA 36          // A smem row stride (words); 36 % 32 == 4
#define GSB 136         // B smem row stride; 136 % 32 == 8
#define GBUF 8960       // floats per gated pipeline buffer (2*64*GSA + 32*GSB)
#define GSMEM_BYTES (2 * GBUF * 4)
#define QBUF 6656       // floats per q pipeline buffer (64*GSA + 32*GSB)

__global__ __launch_bounds__(256, 2) void fused_gemm_kernel(
    const float* __restrict__ kOrig, const float* __restrict__ vOrig,
    const float* __restrict__ bfk, const float* __restrict__ bck,
    const float* __restrict__ bfv, const float* __restrict__ bcv,
    const float* __restrict__ bq,
    float* __restrict__ outk, float* __restrict__ outv)
{
    extern __shared__ float sm[];
    const int r0 = blockIdx.y * 64, n0 = blockIdx.x * 128;
    const int t = threadIdx.x, w = t >> 5, lane = t & 31;
    const int lr = lane >> 2, lc = lane & 3;
    const int wm = (w >> 2) * 32;   // 0 / 32
    const int wn = (w & 3) * 32;    // 0,32,64,96
    const uint32_t sbase = (uint32_t)__cvta_generic_to_shared(sm);

    if (blockIdx.z < 64) {
        // ================= gated body =================
        const int z = blockIdx.z, b = z >> 1, which = z & 1;
        const float* Wf   = which ? g_Wfv : g_Wfk;
        const float* Wc   = which ? g_Wcv : g_Wck;
        const float* bfp  = which ? bfv : bfk;
        const float* bcp  = which ? bcv : bck;
        const float* extc = which ? g_vc : g_kc;
        const float* extra = which ? vOrig : kOrig;
        float* out = which ? outv : outk;

        float accF[2][4][4], accC[2][4][4];
        #pragma unroll
        for (int mf = 0; mf < 2; mf++) {
            int rA = r0 + wm + mf * 16 + lr;
            float bf0 = bfp[rA], bf1 = bfp[rA + 8];
            float bc0 = bcp[rA], bc1 = bcp[rA + 8];
            #pragma unroll
            for (int nf = 0; nf < 4; nf++) {
                accF[mf][nf][0] = bf0; accF[mf][nf][1] = bf0;
                accF[mf][nf][2] = bf1; accF[mf][nf][3] = bf1;
                accC[mf][nf][0] = bc0; accC[mf][nf][1] = bc0;
                accC[mf][nf][2] = bc1; accC[mf][nf][3] = bc1;
            }
        }

        auto issue = [&](int it, int buf) {
            const int k0 = it * 32;
            const uint32_t base = sbase + buf * (GBUF * 4);
            #pragma unroll
            for (int h = 0; h < 2; h++) {
                int a = t + 256 * h;                // 0..511
                int r = a >> 3, c4 = a & 7;
                cpa16(base + (r * GSA + c4 * 4) * 4,
                      Wf + (size_t)(r0 + r) * 288 + k0 + c4 * 4);
                cpa16(base + (2304 + r * GSA + c4 * 4) * 4,
                      Wc + (size_t)(r0 + r) * 288 + k0 + c4 * 4);
            }
            #pragma unroll
            for (int h = 0; h < 4; h++) {
                int bi = t + 256 * h;               // 0..1023
                int r = bi >> 5, c4 = bi & 31;
                int row = k0 + r;
                const float* src = (row < 160)
                    ? (g_x0 + ((size_t)b * 160 + row) * 1024 + n0 + c4 * 4)
                    : (extc + ((size_t)b * 128 + (row - 160)) * 1024 + n0 + c4 * 4);
                cpa16(base + (4608 + r * GSB + c4 * 4) * 4, src);
            }
            CP_COMMIT();
        };

        issue(0, 0);
        #pragma unroll 1
        for (int it = 0; it < 9; it++) {
            if (it < 8) {
                issue(it + 1, (it + 1) & 1);
                asm volatile("cp.async.wait_group 1;" ::: "memory");
            } else {
                asm volatile("cp.async.wait_group 0;" ::: "memory");
            }
            __syncthreads();

            const float* AsF = sm + (it & 1) * GBUF;
            const float* AsC = AsF + 2304;
            const float* Bs  = AsF + 4608;

            #pragma unroll
            for (int kf = 0; kf < 4; kf++) {
                int kk = kf * 8;
                uint32_t aF[2][4], aC[2][4], bb[4][2];
                #pragma unroll
                for (int mf = 0; mf < 2; mf++) {
                    int base = (wm + mf * 16 + lr) * GSA + kk + lc;
                    aF[mf][0] = __float_as_uint(AsF[base]);
                    aF[mf][1] = __float_as_uint(AsF[base + 8 * GSA]);
                    aF[mf][2] = __float_as_uint(AsF[base + 4]);
                    aF[mf][3] = __float_as_uint(AsF[base + 8 * GSA + 4]);
                    aC[mf][0] = __float_as_uint(AsC[base]);
                    aC[mf][1] = __float_as_uint(AsC[base + 8 * GSA]);
                    aC[mf][2] = __float_as_uint(AsC[base + 4]);
                    aC[mf][3] = __float_as_uint(AsC[base + 8 * GSA + 4]);
                }
                #pragma unroll
                for (int nf = 0; nf < 4; nf++) {
                    int base = (kk + lc) * GSB + wn + nf * 8 + lr;
                    bb[nf][0] = __float_as_uint(Bs[base]);
                    bb[nf][1] = __float_as_uint(Bs[base + 4 * GSB]);
                }
                #pragma unroll
                for (int mf = 0; mf < 2; mf++)
                    #pragma unroll
                    for (int nf = 0; nf < 4; nf++) {
                        mma_tf32(accF[mf][nf][0], accF[mf][nf][1], accF[mf][nf][2], accF[mf][nf][3],
                                 aF[mf][0], aF[mf][1], aF[mf][2], aF[mf][3], bb[nf][0], bb[nf][1]);
                        mma_tf32(accC[mf][nf][0], accC[mf][nf][1], accC[mf][nf][2], accC[mf][nf][3],
                                 aC[mf][0], aC[mf][1], aC[mf][2], aC[mf][3], bb[nf][0], bb[nf][1]);
                    }
            }
            __syncthreads();
        }

        #pragma unroll
        for (int mf = 0; mf < 2; mf++) {
            int rA = r0 + wm + mf * 16 + lr;
            #pragma unroll
            for (int nf = 0; nf < 4; nf++) {
                int n = n0 + wn + nf * 8 + 2 * lc;
                #pragma unroll
                for (int h = 0; h < 2; h++) {
                    int row = rA + h * 8;
                    #pragma unroll
                    for (int j = 0; j < 2; j++) {
                        float F  = accF[mf][nf][2 * h + j];
                        float Cc = accC[mf][nf][2 * h + j];
                        float f  = 1.0f / (1.0f + __expf(-F));
                        float cc = fmaxf(Cc, 0.0f);
                        size_t off = ((size_t)(b * 128 + row)) * 1024 + n + j;
                        out[off] = f * extra[off] + cc;
                    }
                }
            }
        }
    } else {
        // ================= q body =================
        const int b = blockIdx.z - 64;

        float acc[2][4][4];
        #pragma unroll
        for (int mf = 0; mf < 2; mf++) {
            int rA = r0 + wm + mf * 16 + lr;
            float b0 = bq[rA], b1 = bq[rA + 8];
            #pragma unroll
            for (int nf = 0; nf < 4; nf++) {
                acc[mf][nf][0] = b0; acc[mf][nf][1] = b0;
                acc[mf][nf][2] = b1; acc[mf][nf][3] = b1;
            }
        }

        auto issue = [&](int it, int buf) {
            const int k0 = it * 32;
            const uint32_t base = sbase + buf * (QBUF * 4);
            #pragma unroll
            for (int h = 0; h < 2; h++) {
                int a = t + 256 * h;
                int r = a >> 3, c4 = a & 7;
                cpa16(base + (r * GSA + c4 * 4) * 4,
                      g_Wq + (size_t)(r0 + r) * 160 + k0 + c4 * 4);
            }
            #pragma unroll
            for (int h = 0; h < 4; h++) {
                int bi = t + 256 * h;
                int r = bi >> 5, c4 = bi & 31;
                cpa16(base + (2304 + r * GSB + c4 * 4) * 4,
                      g_x0 + ((size_t)b * 160 + k0 + r) * 1024 + n0 + c4 * 4);
            }
            CP_COMMIT();
        };

        issue(0, 0);
        #pragma unroll 1
        for (int it = 0; it < 5; it++) {
            if (it < 4) {
                issue(it + 1, (it + 1) & 1);
                asm volatile("cp.async.wait_group 1;" ::: "memory");
            } else {
                asm volatile("cp.async.wait_group 0;" ::: "memory");
            }
            __syncthreads();

            const float* As = sm + (it & 1) * QBUF;
            const float* Bs = As + 2304;

            #pragma unroll
            for (int kf = 0; kf < 4; kf++) {
                int kk = kf * 8;
                uint32_t aa[2][4], bb[4][2];
                #pragma unroll
                for (int mf = 0; mf < 2; mf++) {
                    int base = (wm + mf * 16 + lr) * GSA + kk + lc;
                    aa[mf][0] = __float_as_uint(As[base]);
                    aa[mf][1] = __float_as_uint(As[base + 8 * GSA]);
                    aa[mf][2] = __float_as_uint(As[base + 4]);
                    aa[mf][3] = __float_as_uint(As[base + 8 * GSA + 4]);
                }
                #pragma unroll
                for (int nf = 0; nf < 4; nf++) {
                    int base = (kk + lc) * GSB + wn + nf * 8 + lr;
                    bb[nf][0] = __float_as_uint(Bs[base]);
                    bb[nf][1] = __float_as_uint(Bs[base + 4 * GSB]);
                }
                #pragma unroll
                for (int mf = 0; mf < 2; mf++)
                    #pragma unroll
                    for (int nf = 0; nf < 4; nf++)
                        mma_tf32(acc[mf][nf][0], acc[mf][nf][1], acc[mf][nf][2], acc[mf][nf][3],
                                 aa[mf][0], aa[mf][1], aa[mf][2], aa[mf][3], bb[nf][0], bb[nf][1]);
            }
            __syncthreads();
        }

        #pragma unroll
        for (int mf = 0; mf < 2; mf++) {
            int rA = r0 + wm + mf * 16 + lr;
            #pragma unroll
            for (int nf = 0; nf < 4; nf++) {
                int n = n0 + wn + nf * 8 + 2 * lc;
                #pragma unroll
                for (int h = 0; h < 2; h++) {
                    int row = rA + h * 8;
                    #pragma unroll
                    for (int j = 0; j < 2; j++) {
                        float val = fmaxf(acc[mf][nf][2 * h + j], 0.0f);
                        g_q[((size_t)(b * 128 + row)) * 1024 + n + j] = f2tff(val);
                    }
                }
            }
        }
    }
}

// ---------------------------------------------------------------------------
// Causal attention, flash style, 256 threads / 32-query tiles.
// smem 97.7 KB -> 2 CTAs per SM; phases of the two CTAs interleave so the
// tensor pipe stays fed during softmax/barriers.
// S phase : 2M x 4N warps, warp tile 16 q-rows x 16 keys.
// PV phase: warp tile 16 q-rows x 32 v-channels.
// Single-buffered K/V with hidden cp.async (K_{i+1} after S_i, V_{i+1}
// after PV_i). Softmax: 8 threads per row.
// ---------------------------------------------------------------------------
#define SQ 132
#define SK 72
#define SV 68
#define SP 68

#define OFF_QT 0                          // 32*SQ = 4224
#define OFF_KS 4224                       // 128*SK = 9216
#define OFF_VS (OFF_KS + 128 * SK)        // 13440; 128*SV = 8704
#define OFF_PS (OFF_VS + 128 * SV)        // 22144; 32*SP = 2176
#define OFF_MAX (OFF_PS + 32 * SP)        // 24320
#define OFF_SUM (OFF_MAX + 32)
#define OFF_ALP (OFF_SUM + 32)
#define ATTN_SMEM_FLOATS (OFF_ALP + 32)   // 24416
#define ATTN_SMEM_BYTES (ATTN_SMEM_FLOATS * 4)   // 97664

__global__ __launch_bounds__(256, 2) void attn_kernel(float* __restrict__ out)
{
    extern __shared__ float sm[];
    float* Qt = sm + OFF_QT;
    float* Ks = sm + OFF_KS;
    float* Vs = sm + OFF_VS;
    float* Ps = sm + OFF_PS;
    float* sMax = sm + OFF_MAX;
    float* sSum = sm + OFF_SUM;
    float* sAlpha = sm + OFF_ALP;

    const int b = blockIdx.y;
    const int qt = 31 - blockIdx.x;       // heavy q-tiles first
    const int n0 = qt * 32;
    const int mtMax = qt >> 1;            // last 64-key tile index
    const int doff = n0 - mtMax * 64;     // 0 (even qt) or 32 (odd qt)
    const int t = threadIdx.x, w = t >> 5, lane = t & 31;
    const int lr = lane >> 2, lc = lane & 3;
    const int wm  = (w >> 2) * 16;        // 0/16: q-row group
    const int wnS = (w & 3) * 16;         // S-phase key cols
    const int wnV = (w & 3) * 32;         // PV-phase v-channels
    const float scale = 0.08838834764831845f;
    const uint32_t sbase = (uint32_t)__cvta_generic_to_shared(sm);

    auto issue_k = [&](int mt) {
        const int m0 = mt * 64;
        const uint32_t kb = sbase + OFF_KS * 4;
        #pragma unroll
        for (int h = 0; h < 8; h++) {
            int idx = t + 256 * h;            // 0..2047
            int c = idx >> 4, m4 = idx & 15;
            cpa16(kb + (c * SK + m4 * 4) * 4,
                  g_kc + ((size_t)(b * 128 + c)) * 1024 + m0 + m4 * 4);
        }
        CP_COMMIT();
    };
    auto issue_v = [&](int mt) {
        const int m0 = mt * 64;
        const uint32_t vb = sbase + OFF_VS * 4;
        #pragma unroll
        for (int h = 0; h < 8; h++) {
            int idx = t + 256 * h;
            int c = idx >> 4, m4 = idx & 15;
            cpa16(vb + (c * SV + m4 * 4) * 4,
                  g_vc + ((size_t)(b * 128 + c)) * 1024 + m0 + m4 * 4);
        }
        CP_COMMIT();
    };

    issue_k(0);
    issue_v(0);

    // Q tile transposed: Qt[i][c], i in [0,32), c in [0,128)
    #pragma unroll
    for (int e = 0; e < 16; e++) {
        int idx = t + 256 * e;              // 0..4095
        int c = idx >> 5, i = idx & 31;
        Qt[i * SQ + c] = g_q[((size_t)(b * 128 + c)) * 1024 + n0 + i];
    }
    if (t < 32) { sMax[t] = -1e30f; sSum[t] = 0.0f; }

    float O[4][4];
    #pragma unroll
    for (int nf = 0; nf < 4; nf++)
        #pragma unroll
        for (int j = 0; j < 4; j++) O[nf][j] = 0.0f;

    #pragma unroll 1
    for (int mt = 0; mt <= mtMax; mt++) {
        // K_mt ready (pending {K_mt, V_mt} -> wait<=1 drains K_mt)
        asm volatile("cp.async.wait_group 1;" ::: "memory");
        __syncthreads();

        // ---- S = Q^T K (warp tile 16x16) ----
        float S[2][4];
        #pragma unroll
        for (int nf = 0; nf < 2; nf++)
            #pragma unroll
            for (int j = 0; j < 4; j++) S[nf][j] = 0.0f;

        #pragma unroll
        for (int kf = 0; kf < 16; kf++) {
            int kc = kf * 8;
            int abase = (wm + lr) * SQ + kc + lc;
            uint32_t a0 = __float_as_uint(Qt[abase]);
            uint32_t a1 = __float_as_uint(Qt[abase + 8 * SQ]);
            uint32_t a2 = __float_as_uint(Qt[abase + 4]);
            uint32_t a3 = __float_as_uint(Qt[abase + 8 * SQ + 4]);
            #pragma unroll
            for (int nf = 0; nf < 2; nf++) {
                int bbase = (kc + lc) * SK + wnS + nf * 8 + lr;
                uint32_t b0 = __float_as_uint(Ks[bbase]);
                uint32_t b1 = __float_as_uint(Ks[bbase + 4 * SK]);
                mma_tf32(S[nf][0], S[nf][1], S[nf][2], S[nf][3], a0, a1, a2, a3, b0, b1);
            }
        }
        #pragma unroll
        for (int nf = 0; nf < 2; nf++) {
            int col = wnS + nf * 8 + 2 * lc;
            int row = wm + lr;
            Ps[row * SP + col]           = S[nf][0] * scale;
            Ps[row * SP + col + 1]       = S[nf][1] * scale;
            Ps[(row + 8) * SP + col]     = S[nf][2] * scale;
            Ps[(row + 8) * SP + col + 1] = S[nf][3] * scale;
        }
        __syncthreads();            // S reads of Ks done, Ps visible

        // Prefetch next K (hidden behind softmax + PV)
        if (mt < mtMax) issue_k(mt + 1);

        // ---- Online softmax: 8 threads per row (32 rows) ----
        {
            int r = t >> 3, qd = t & 7;
            bool diag = (mt == mtMax);
            float vals[8];
            float tm = -1e30f;
            #pragma unroll
            for (int j = 0; j < 8; j++) {
                int m = qd * 8 + j;
                float s = Ps[r * SP + m];
                if (diag && m > doff + r) s = -1e30f;
                vals[j] = s;
                tm = fmaxf(tm, s);
            }
            tm = fmaxf(tm, __shfl_xor_sync(0xffffffffu, tm, 1));
            tm = fmaxf(tm, __shfl_xor_sync(0xffffffffu, tm, 2));
            tm = fmaxf(tm, __shfl_xor_sync(0xffffffffu, tm, 4));
            float rm = sMax[r];
            float nm = fmaxf(rm, tm);
            float ps = 0.0f;
            #pragma unroll
            for (int j = 0; j < 8; j++) {
                float p = f2tff(__expf(vals[j] - nm));
                Ps[r * SP + qd * 8 + j] = p;
                ps += p;
            }
            ps += __shfl_xor_sync(0xffffffffu, ps, 1);
            ps += __shfl_xor_sync(0xffffffffu, ps, 2);
            ps += __shfl_xor_sync(0xffffffffu, ps, 4);
            float alpha = __expf(rm - nm);
            if (qd == 0) {
                sSum[r] = sSum[r] * alpha + ps;
                sMax[r] = nm;
                sAlpha[r] = alpha;
            }
        }

        // V_mt ready (pending {V_mt, K_{mt+1}} -> wait<=1; last iter wait 0)
        if (mt < mtMax) {
            asm volatile("cp.async.wait_group 1;" ::: "memory");
        } else {
            asm volatile("cp.async.wait_group 0;" ::: "memory");
        }
        __syncthreads();            // P + stats visible, V ready

        // ---- O = O*alpha + P @ V^T (warp tile 16 rows x 32 channels) ----
        float aLo = sAlpha[wm + lr], aHi = sAlpha[wm + lr + 8];
        #pragma unroll
        for (int nf = 0; nf < 4; nf++) {
            O[nf][0] *= aLo; O[nf][1] *= aLo;
            O[nf][2] *= aHi; O[nf][3] *= aHi;
        }
        #pragma unroll
        for (int kf = 0; kf < 8; kf++) {
            int kc = kf * 8;
            int abase = (wm + lr) * SP + kc + lc;
            uint32_t a0 = __float_as_uint(Ps[abase]);
            uint32_t a1 = __float_as_uint(Ps[abase + 8 * SP]);
            uint32_t a2 = __float_as_uint(Ps[abase + 4]);
            uint32_t a3 = __float_as_uint(Ps[abase + 8 * SP + 4]);
            #pragma unroll
            for (int nf = 0; nf < 4; nf++) {
                int vb = wnV + nf * 8 + lr;
                int bbase = vb * SV + kc + lc;
                uint32_t b0 = __float_as_uint(Vs[bbase]);
                uint32_t b1 = __float_as_uint(Vs[bbase + 4]);
                mma_tf32(O[nf][0], O[nf][1], O[nf][2], O[nf][3], a0, a1, a2, a3, b0, b1);
            }
        }
        __syncthreads();            // PV reads of Vs done

        // Prefetch next V (hidden behind next S phase)
        if (mt < mtMax) issue_v(mt + 1);
    }

    float invLo = 1.0f / sSum[wm + lr];
    float invHi = 1.0f / sSum[wm + lr + 8];
    int nLo = n0 + wm + lr, nHi = nLo + 8;
    #pragma unroll
    for (int nf = 0; nf < 4; nf++) {
        int vc = wnV + nf * 8 + 2 * lc;
        out[((size_t)(b * 128 + vc))     * 1024 + nLo] = O[nf][0] * invLo;
        out[((size_t)(b * 128 + vc + 1)) * 1024 + nLo] = O[nf][1] * invLo;
        out[((size_t)(b * 128 + vc))     * 1024 + nHi] = O[nf][2] * invHi;
        out[((size_t)(b * 128 + vc + 1)) * 1024 + nHi] = O[nf][3] * invHi;
    }
}

// ---------------------------------------------------------------------------
// Launch (single stream, graph-capturable)
// ---------------------------------------------------------------------------
extern "C" void kernel_launch(void* const* d_in, const int* in_sizes, int n_in,
                              void* d_out, int out_size)
{
    const float* x   = (const float*)d_in[0];
    const float* k   = (const float*)d_in[1];
    const float* v   = (const float*)d_in[2];
    const float* Wq  = (const float*)d_in[3];
    const float* bq  = (const float*)d_in[4];
    const float* Wfk = (const float*)d_in[5];
    const float* bfk = (const float*)d_in[6];
    const float* Wck = (const float*)d_in[7];
    const float* bck = (const float*)d_in[8];
    const float* Wfv = (const float*)d_in[9];
    const float* bfv = (const float*)d_in[10];
    const float* Wcv = (const float*)d_in[11];
    const float* bcv = (const float*)d_in[12];

    float* out2 = (float*)d_out;
    float* kn   = out2 + (size_t)32 * 128 * 1024;
    float* vn   = kn   + (size_t)32 * 128 * 1024;

    cudaFuncSetAttribute(fused_gemm_kernel, cudaFuncAttributeMaxDynamicSharedMemorySize, GSMEM_BYTES);
    cudaFuncSetAttribute(attn_kernel, cudaFuncAttributeMaxDynamicSharedMemorySize, ATTN_SMEM_BYTES);

    pos_kernel<<<32, 1024>>>();
    pack_kernel<<<(PACK_TOTAL + 255) / 256, 256>>>(x, k, v, Wq, Wfk, Wck, Wfv, Wcv);
    fused_gemm_kernel<<<dim3(8, 2, 96), 256, GSMEM_BYTES>>>(
        k, v, bfk, bck, bfv, bcv, bq, kn, vn);
    attn_kernel<<<dim3(32, 32), 256, ATTN_SMEM_BYTES>>>(out2);
}

// round 7
// speedup vs baseline: 1.1193x; 1.1193x over previous
#include <cuda_runtime.h>
#include <math.h>
#include <stdint.h>

// ---------------------------------------------------------------------------
// Scratch (__device__ globals; no allocation allowed)
// ---------------------------------------------------------------------------
__device__ float g_pos[32 * 1024];              // [32 ch][1024], fp32
__device__ float g_x0[32 * 160 * 1024];         // tf32 [B][160][N]  (x|pos)
__device__ float g_kc[32 * 128 * 1024];         // tf32 k
__device__ float g_vc[32 * 128 * 1024];         // tf32 v
__device__ float g_q [32 * 128 * 1024];         // tf32 q
__device__ float g_Wq [128 * 160];              // tf32 weights
__device__ float g_Wfk[128 * 288];
__device__ float g_Wck[128 * 288];
__device__ float g_Wfv[128 * 288];
__device__ float g_Wcv[128 * 288];

// ---------------------------------------------------------------------------
// Helpers
// ---------------------------------------------------------------------------
__device__ __forceinline__ uint32_t f2tf(float x) {
    uint32_t u;
    asm("cvt.rna.tf32.f32 %0, %1;" : "=r"(u) : "f"(x));
    return u;
}
__device__ __forceinline__ float f2tff(float x) { return __uint_as_float(f2tf(x)); }

__device__ __forceinline__ void mma_tf32(
    float& d0, float& d1, float& d2, float& d3,
    uint32_t a0, uint32_t a1, uint32_t a2, uint32_t a3,
    uint32_t b0, uint32_t b1)
{
    asm volatile(
        "mma.sync.aligned.m16n8k8.row.col.f32.tf32.tf32.f32 "
        "{%0,%1,%2,%3}, {%4,%5,%6,%7}, {%8,%9}, {%0,%1,%2,%3};"
        : "+f"(d0), "+f"(d1), "+f"(d2), "+f"(d3)
        : "r"(a0), "r"(a1), "r"(a2), "r"(a3), "r"(b0), "r"(b1));
}

__device__ __forceinline__ void cpa16(uint32_t dst, const void* src) {
    asm volatile("cp.async.ca.shared.global [%0], [%1], 16;" :: "r"(dst), "l"(src));
}
#define CP_COMMIT() asm volatile("cp.async.commit_group;" ::: "memory")

// ---------------------------------------------------------------------------
// Positional embedding (faithful to numpy .view reinterpret)
// ---------------------------------------------------------------------------
__global__ void pos_kernel() {
    int idx = blockIdx.x * blockDim.x + threadIdx.x;
    if (idx >= 32 * 1024) return;
    int c = idx >> 10, n = idx & 1023;
    int y = n >> 5, x = n & 31;
    int i = (c < 16) ? (c * 32 + y) : ((c - 16) * 32 + x);
    int p = i >> 4, j = i & 15;
    float r = 0.0f;
    if (p != 0) {
        double denom = pow(10000.0, (double)(2 * (j >> 1)) / 16.0);
        double val = (double)p / denom;
        r = (j & 1) ? (float)cos(val) : (float)sin(val);
    }
    g_pos[idx] = r;
}

// ---------------------------------------------------------------------------
// Pack: tf32-round inputs AND weights into scratch (one launch)
// ---------------------------------------------------------------------------
__device__ __forceinline__ float4 tf4(float4 s) {
    s.x = f2tff(s.x); s.y = f2tff(s.y); s.z = f2tff(s.z); s.w = f2tff(s.w);
    return s;
}

#define PACK_NX0 (32 * 160 * 256)
#define PACK_NKV (32 * 128 * 256)
#define PACK_DATA (PACK_NX0 + 2 * PACK_NKV)
#define PACK_TOTAL (PACK_DATA + 128 * 288)

__global__ void pack_kernel(const float* __restrict__ x,
                            const float* __restrict__ k,
                            const float* __restrict__ v,
                            const float* __restrict__ Wq,
                            const float* __restrict__ Wfk, const float* __restrict__ Wck,
                            const float* __restrict__ Wfv, const float* __restrict__ Wcv)
{
    int i = blockIdx.x * blockDim.x + threadIdx.x;
    if (i < PACK_NX0) {
        int n4 = i & 255;
        int cb = i >> 8;
        int c = cb % 160, b = cb / 160;
        float4 s;
        if (c < 128)
            s = ((const float4*)x)[(size_t)(b * 128 + c) * 256 + n4];
        else
            s = ((const float4*)g_pos)[(c - 128) * 256 + n4];
        ((float4*)g_x0)[i] = tf4(s);
    } else if (i < PACK_NX0 + PACK_NKV) {
        int j = i - PACK_NX0;
        ((float4*)g_kc)[j] = tf4(((const float4*)k)[j]);
    } else if (i < PACK_DATA) {
        int j = i - PACK_NX0 - PACK_NKV;
        ((float4*)g_vc)[j] = tf4(((const float4*)v)[j]);
    } else {
        int j = i - PACK_DATA;                 // 0 .. 128*288-1
        if (j < 128 * 160) g_Wq[j] = f2tff(Wq[j]);
        g_Wfk[j] = f2tff(Wfk[j]);
        g_Wck[j] = f2tff(Wck[j]);
        g_Wfv[j] = f2tff(Wfv[j]);
        g_Wcv[j] = f2tff(Wcv[j]);
    }
}

// ---------------------------------------------------------------------------
// Fused GEMM kernel (unchanged, proven):
//   z in [0,64)  : gated highway update (z = b*2 + which), K=288, 9 steps
//   z in [64,96) : q = tf32(relu(Wq@x0+bq)) for b = z-64, K=160, 5 steps
// ---------------------------------------------------------------------------
#define GSA 36          // A smem row stride (words); 36 % 32 == 4
#define GSB 136         // B smem row stride; 136 % 32 == 8
#define GBUF 8960       // floats per gated pipeline buffer (2*64*GSA + 32*GSB)
#define GSMEM_BYTES (2 * GBUF * 4)
#define QBUF 6656       // floats per q pipeline buffer (64*GSA + 32*GSB)

__global__ __launch_bounds__(256, 2) void fused_gemm_kernel(
    const float* __restrict__ kOrig, const float* __restrict__ vOrig,
    const float* __restrict__ bfk, const float* __restrict__ bck,
    const float* __restrict__ bfv, const float* __restrict__ bcv,
    const float* __restrict__ bq,
    float* __restrict__ outk, float* __restrict__ outv)
{
    extern __shared__ float sm[];
    const int r0 = blockIdx.y * 64, n0 = blockIdx.x * 128;
    const int t = threadIdx.x, w = t >> 5, lane = t & 31;
    const int lr = lane >> 2, lc = lane & 3;
    const int wm = (w >> 2) * 32;   // 0 / 32
    const int wn = (w & 3) * 32;    // 0,32,64,96
    const uint32_t sbase = (uint32_t)__cvta_generic_to_shared(sm);

    if (blockIdx.z < 64) {
        // ================= gated body =================
        const int z = blockIdx.z, b = z >> 1, which = z & 1;
        const float* Wf   = which ? g_Wfv : g_Wfk;
        const float* Wc   = which ? g_Wcv : g_Wck;
        const float* bfp  = which ? bfv : bfk;
        const float* bcp  = which ? bcv : bck;
        const float* extc = which ? g_vc : g_kc;
        const float* extra = which ? vOrig : kOrig;
        float* out = which ? outv : outk;

        float accF[2][4][4], accC[2][4][4];
        #pragma unroll
        for (int mf = 0; mf < 2; mf++) {
            int rA = r0 + wm + mf * 16 + lr;
            float bf0 = bfp[rA], bf1 = bfp[rA + 8];
            float bc0 = bcp[rA], bc1 = bcp[rA + 8];
            #pragma unroll
            for (int nf = 0; nf < 4; nf++) {
                accF[mf][nf][0] = bf0; accF[mf][nf][1] = bf0;
                accF[mf][nf][2] = bf1; accF[mf][nf][3] = bf1;
                accC[mf][nf][0] = bc0; accC[mf][nf][1] = bc0;
                accC[mf][nf][2] = bc1; accC[mf][nf][3] = bc1;
            }
        }

        auto issue = [&](int it, int buf) {
            const int k0 = it * 32;
            const uint32_t base = sbase + buf * (GBUF * 4);
            #pragma unroll
            for (int h = 0; h < 2; h++) {
                int a = t + 256 * h;                // 0..511
                int r = a >> 3, c4 = a & 7;
                cpa16(base + (r * GSA + c4 * 4) * 4,
                      Wf + (size_t)(r0 + r) * 288 + k0 + c4 * 4);
                cpa16(base + (2304 + r * GSA + c4 * 4) * 4,
                      Wc + (size_t)(r0 + r) * 288 + k0 + c4 * 4);
            }
            #pragma unroll
            for (int h = 0; h < 4; h++) {
                int bi = t + 256 * h;               // 0..1023
                int r = bi >> 5, c4 = bi & 31;
                int row = k0 + r;
                const float* src = (row < 160)
                    ? (g_x0 + ((size_t)b * 160 + row) * 1024 + n0 + c4 * 4)
                    : (extc + ((size_t)b * 128 + (row - 160)) * 1024 + n0 + c4 * 4);
                cpa16(base + (4608 + r * GSB + c4 * 4) * 4, src);
            }
            CP_COMMIT();
        };

        issue(0, 0);
        #pragma unroll 1
        for (int it = 0; it < 9; it++) {
            if (it < 8) {
                issue(it + 1, (it + 1) & 1);
                asm volatile("cp.async.wait_group 1;" ::: "memory");
            } else {
                asm volatile("cp.async.wait_group 0;" ::: "memory");
            }
            __syncthreads();

            const float* AsF = sm + (it & 1) * GBUF;
            const float* AsC = AsF + 2304;
            const float* Bs  = AsF + 4608;

            #pragma unroll
            for (int kf = 0; kf < 4; kf++) {
                int kk = kf * 8;
                uint32_t aF[2][4], aC[2][4], bb[4][2];
                #pragma unroll
                for (int mf = 0; mf < 2; mf++) {
                    int base = (wm + mf * 16 + lr) * GSA + kk + lc;
                    aF[mf][0] = __float_as_uint(AsF[base]);
                    aF[mf][1] = __float_as_uint(AsF[base + 8 * GSA]);
                    aF[mf][2] = __float_as_uint(AsF[base + 4]);
                    aF[mf][3] = __float_as_uint(AsF[base + 8 * GSA + 4]);
                    aC[mf][0] = __float_as_uint(AsC[base]);
                    aC[mf][1] = __float_as_uint(AsC[base + 8 * GSA]);
                    aC[mf][2] = __float_as_uint(AsC[base + 4]);
                    aC[mf][3] = __float_as_uint(AsC[base + 8 * GSA + 4]);
                }
                #pragma unroll
                for (int nf = 0; nf < 4; nf++) {
                    int base = (kk + lc) * GSB + wn + nf * 8 + lr;
                    bb[nf][0] = __float_as_uint(Bs[base]);
                    bb[nf][1] = __float_as_uint(Bs[base + 4 * GSB]);
                }
                #pragma unroll
                for (int mf = 0; mf < 2; mf++)
                    #pragma unroll
                    for (int nf = 0; nf < 4; nf++) {
                        mma_tf32(accF[mf][nf][0], accF[mf][nf][1], accF[mf][nf][2], accF[mf][nf][3],
                                 aF[mf][0], aF[mf][1], aF[mf][2], aF[mf][3], bb[nf][0], bb[nf][1]);
                        mma_tf32(accC[mf][nf][0], accC[mf][nf][1], accC[mf][nf][2], accC[mf][nf][3],
                                 aC[mf][0], aC[mf][1], aC[mf][2], aC[mf][3], bb[nf][0], bb[nf][1]);
                    }
            }
            __syncthreads();
        }

        #pragma unroll
        for (int mf = 0; mf < 2; mf++) {
            int rA = r0 + wm + mf * 16 + lr;
            #pragma unroll
            for (int nf = 0; nf < 4; nf++) {
                int n = n0 + wn + nf * 8 + 2 * lc;
                #pragma unroll
                for (int h = 0; h < 2; h++) {
                    int row = rA + h * 8;
                    #pragma unroll
                    for (int j = 0; j < 2; j++) {
                        float F  = accF[mf][nf][2 * h + j];
                        float Cc = accC[mf][nf][2 * h + j];
                        float f  = 1.0f / (1.0f + __expf(-F));
                        float cc = fmaxf(Cc, 0.0f);
                        size_t off = ((size_t)(b * 128 + row)) * 1024 + n + j;
                        out[off] = f * extra[off] + cc;
                    }
                }
            }
        }
    } else {
        // ================= q body =================
        const int b = blockIdx.z - 64;

        float acc[2][4][4];
        #pragma unroll
        for (int mf = 0; mf < 2; mf++) {
            int rA = r0 + wm + mf * 16 + lr;
            float b0 = bq[rA], b1 = bq[rA + 8];
            #pragma unroll
            for (int nf = 0; nf < 4; nf++) {
                acc[mf][nf][0] = b0; acc[mf][nf][1] = b0;
                acc[mf][nf][2] = b1; acc[mf][nf][3] = b1;
            }
        }

        auto issue = [&](int it, int buf) {
            const int k0 = it * 32;
            const uint32_t base = sbase + buf * (QBUF * 4);
            #pragma unroll
            for (int h = 0; h < 2; h++) {
                int a = t + 256 * h;
                int r = a >> 3, c4 = a & 7;
                cpa16(base + (r * GSA + c4 * 4) * 4,
                      g_Wq + (size_t)(r0 + r) * 160 + k0 + c4 * 4);
            }
            #pragma unroll
            for (int h = 0; h < 4; h++) {
                int bi = t + 256 * h;
                int r = bi >> 5, c4 = bi & 31;
                cpa16(base + (2304 + r * GSB + c4 * 4) * 4,
                      g_x0 + ((size_t)b * 160 + k0 + r) * 1024 + n0 + c4 * 4);
            }
            CP_COMMIT();
        };

        issue(0, 0);
        #pragma unroll 1
        for (int it = 0; it < 5; it++) {
            if (it < 4) {
                issue(it + 1, (it + 1) & 1);
                asm volatile("cp.async.wait_group 1;" ::: "memory");
            } else {
                asm volatile("cp.async.wait_group 0;" ::: "memory");
            }
            __syncthreads();

            const float* As = sm + (it & 1) * QBUF;
            const float* Bs = As + 2304;

            #pragma unroll
            for (int kf = 0; kf < 4; kf++) {
                int kk = kf * 8;
                uint32_t aa[2][4], bb[4][2];
                #pragma unroll
                for (int mf = 0; mf < 2; mf++) {
                    int base = (wm + mf * 16 + lr) * GSA + kk + lc;
                    aa[mf][0] = __float_as_uint(As[base]);
                    aa[mf][1] = __float_as_uint(As[base + 8 * GSA]);
                    aa[mf][2] = __float_as_uint(As[base + 4]);
                    aa[mf][3] = __float_as_uint(As[base + 8 * GSA + 4]);
                }
                #pragma unroll
                for (int nf = 0; nf < 4; nf++) {
                    int base = (kk + lc) * GSB + wn + nf * 8 + lr;
                    bb[nf][0] = __float_as_uint(Bs[base]);
                    bb[nf][1] = __float_as_uint(Bs[base + 4 * GSB]);
                }
                #pragma unroll
                for (int mf = 0; mf < 2; mf++)
                    #pragma unroll
                    for (int nf = 0; nf < 4; nf++)
                        mma_tf32(acc[mf][nf][0], acc[mf][nf][1], acc[mf][nf][2], acc[mf][nf][3],
                                 aa[mf][0], aa[mf][1], aa[mf][2], aa[mf][3], bb[nf][0], bb[nf][1]);
            }
            __syncthreads();
        }

        #pragma unroll
        for (int mf = 0; mf < 2; mf++) {
            int rA = r0 + wm + mf * 16 + lr;
            #pragma unroll
            for (int nf = 0; nf < 4; nf++) {
                int n = n0 + wn + nf * 8 + 2 * lc;
                #pragma unroll
                for (int h = 0; h < 2; h++) {
                    int row = rA + h * 8;
                    #pragma unroll
                    for (int j = 0; j < 2; j++) {
                        float val = fmaxf(acc[mf][nf][2 * h + j], 0.0f);
                        g_q[((size_t)(b * 128 + row)) * 1024 + n + j] = f2tff(val);
                    }
                }
            }
        }
    }
}

// ---------------------------------------------------------------------------
// Causal attention, FA2-style: CTA = 128 queries, 8 warps, 256 threads.
// Each warp owns 16 q-rows x full 64-key width:
//   - softmax stats (max/sum/alpha) fully in registers (shfl over 4 lanes/row)
//   - P staged in warp-PRIVATE smem strip (no CTA barrier, __syncwarp only)
//   - O accumulators in registers (16 rows x 128 v-channels per warp)
// Q stored channel-major (Qs[c][n], pad 136): cp.async fill, conflict-free
// A-fragment reads. Single-buffer K/V with hidden prefetch.
// smem = 172 KB, 1 CTA/SM. Grid (8 q-tiles, 32 b), heavy tiles first.
// ---------------------------------------------------------------------------
#define SQS 136   // Qs stride: 128 n + 8 pad
#define SK  72    // Ks stride: 64 keys + 8 pad
#define SV  68    // Vs stride: 64 keys + 4 pad
#define SP  68    // Ps stride: 64 keys + 4 pad

#define OFF_QS 0                          // 128*136 = 17408
#define OFF_KS 17408                      // 128*72  = 9216
#define OFF_VS (OFF_KS + 128 * SK)        // 26624;  128*68 = 8704
#define OFF_PS (OFF_VS + 128 * SV)        // 35328;  128*68 = 8704
#define ATTN_SMEM_FLOATS (OFF_PS + 128 * SP)   // 44032
#define ATTN_SMEM_BYTES (ATTN_SMEM_FLOATS * 4) // 176128 (< 227KB)

__global__ __launch_bounds__(256, 1) void attn_kernel(float* __restrict__ out)
{
    extern __shared__ float sm[];
    float* Qs = sm + OFF_QS;
    float* Ks = sm + OFF_KS;
    float* Vs = sm + OFF_VS;
    float* Ps = sm + OFF_PS;

    const int b = blockIdx.y;
    const int qt = 7 - blockIdx.x;        // heavy q-tiles first
    const int n0 = qt * 128;
    const int mtMax = 2 * qt + 1;
    const int t = threadIdx.x, w = t >> 5, lane = t & 31;
    const int lr = lane >> 2, lc = lane & 3;
    const int wq = w * 16;                // warp's local q-row base
    const float scale = 0.08838834764831845f;
    const uint32_t sbase = (uint32_t)__cvta_generic_to_shared(sm);

    auto issue_k = [&](int mt) {
        const int m0 = mt * 64;
        const uint32_t kb = sbase + OFF_KS * 4;
        #pragma unroll
        for (int h = 0; h < 8; h++) {
            int idx = t + 256 * h;            // 0..2047
            int c = idx >> 4, m4 = idx & 15;
            cpa16(kb + (c * SK + m4 * 4) * 4,
                  g_kc + ((size_t)(b * 128 + c)) * 1024 + m0 + m4 * 4);
        }
        CP_COMMIT();
    };
    auto issue_v = [&](int mt) {
        const int m0 = mt * 64;
        const uint32_t vb = sbase + OFF_VS * 4;
        #pragma unroll
        for (int h = 0; h < 8; h++) {
            int idx = t + 256 * h;
            int c = idx >> 4, m4 = idx & 15;
            cpa16(vb + (c * SV + m4 * 4) * 4,
                  g_vc + ((size_t)(b * 128 + c)) * 1024 + m0 + m4 * 4);
        }
        CP_COMMIT();
    };

    // Q fill (group 0): Qs[c][n-local], channel-major, conflict-free
    {
        const uint32_t qb = sbase + OFF_QS * 4;
        #pragma unroll
        for (int h = 0; h < 16; h++) {
            int idx = t + 256 * h;            // 0..4095
            int c = idx >> 5, i4 = idx & 31;
            cpa16(qb + (c * SQS + i4 * 4) * 4,
                  g_q + ((size_t)(b * 128 + c)) * 1024 + n0 + i4 * 4);
        }
        CP_COMMIT();
    }
    issue_k(0);
    issue_v(0);

    // Running stats (registers, per thread: rows wq+lr and wq+lr+8)
    float mLo = -1e30f, mHi = -1e30f, lLo = 0.0f, lHi = 0.0f;
    float O[16][4];
    #pragma unroll
    for (int nb = 0; nb < 16; nb++)
        #pragma unroll
        for (int j = 0; j < 4; j++) O[nb][j] = 0.0f;

    const int rowLo = n0 + wq + lr;
    const int rowHi = rowLo + 8;

    #pragma unroll 1
    for (int mt = 0; mt <= mtMax; mt++) {
        const int m0 = mt * 64;
        // Q (first iter) + K(mt) ready; V(mt) may still be in flight
        asm volatile("cp.async.wait_group 1;" ::: "memory");
        __syncthreads();

        // ---- S = Q^T K : warp tile 16 x 64 (nf=8) ----
        float S[8][4];
        #pragma unroll
        for (int nb = 0; nb < 8; nb++)
            #pragma unroll
            for (int j = 0; j < 4; j++) S[nb][j] = 0.0f;

        #pragma unroll
        for (int kf = 0; kf < 16; kf++) {
            int kc = kf * 8;
            int abase = (kc + lc) * SQS + wq + lr;
            uint32_t a0 = __float_as_uint(Qs[abase]);
            uint32_t a1 = __float_as_uint(Qs[abase + 8]);           // row+8
            uint32_t a2 = __float_as_uint(Qs[abase + 4 * SQS]);     // k+4
            uint32_t a3 = __float_as_uint(Qs[abase + 4 * SQS + 8]);
            #pragma unroll
            for (int nb = 0; nb < 8; nb++) {
                int bbase = (kc + lc) * SK + nb * 8 + lr;
                uint32_t b0 = __float_as_uint(Ks[bbase]);
                uint32_t b1 = __float_as_uint(Ks[bbase + 4 * SK]);
                mma_tf32(S[nb][0], S[nb][1], S[nb][2], S[nb][3], a0, a1, a2, a3, b0, b1);
            }
        }
        __syncthreads();                  // all warps done reading Ks
        if (mt < mtMax) issue_k(mt + 1);  // hidden behind softmax + PV

        // ---- In-register online softmax ----
        {
            const bool needMask = (m0 + 63 > n0 + wq);
            float tmLo = -1e30f, tmHi = -1e30f;
            #pragma unroll
            for (int nb = 0; nb < 8; nb++) {
                int c0 = m0 + nb * 8 + 2 * lc, c1 = c0 + 1;
                float s0 = S[nb][0] * scale, s1 = S[nb][1] * scale;
                float s2 = S[nb][2] * scale, s3 = S[nb][3] * scale;
                if (needMask) {
                    if (c0 > rowLo) s0 = -1e30f;
                    if (c1 > rowLo) s1 = -1e30f;
                    if (c0 > rowHi) s2 = -1e30f;
                    if (c1 > rowHi) s3 = -1e30f;
                }
                S[nb][0] = s0; S[nb][1] = s1; S[nb][2] = s2; S[nb][3] = s3;
                tmLo = fmaxf(tmLo, fmaxf(s0, s1));
                tmHi = fmaxf(tmHi, fmaxf(s2, s3));
            }
            tmLo = fmaxf(tmLo, __shfl_xor_sync(0xffffffffu, tmLo, 1));
            tmLo = fmaxf(tmLo, __shfl_xor_sync(0xffffffffu, tmLo, 2));
            tmHi = fmaxf(tmHi, __shfl_xor_sync(0xffffffffu, tmHi, 1));
            tmHi = fmaxf(tmHi, __shfl_xor_sync(0xffffffffu, tmHi, 2));
            float nmLo = fmaxf(mLo, tmLo), nmHi = fmaxf(mHi, tmHi);
            float aLo = __expf(mLo - nmLo), aHi = __expf(mHi - nmHi);
            mLo = nmLo; mHi = nmHi;
            float sLoSum = 0.0f, sHiSum = 0.0f;
            #pragma unroll
            for (int nb = 0; nb < 8; nb++) {
                float p0 = f2tff(__expf(S[nb][0] - nmLo));
                float p1 = f2tff(__expf(S[nb][1] - nmLo));
                float p2 = f2tff(__expf(S[nb][2] - nmHi));
                float p3 = f2tff(__expf(S[nb][3] - nmHi));
                sLoSum += p0 + p1;
                sHiSum += p2 + p3;
                int pb = (wq + lr) * SP + nb * 8 + 2 * lc;
                *(float2*)&Ps[pb]           = make_float2(p0, p1);
                *(float2*)&Ps[pb + 8 * SP]  = make_float2(p2, p3);
            }
            sLoSum += __shfl_xor_sync(0xffffffffu, sLoSum, 1);
            sLoSum += __shfl_xor_sync(0xffffffffu, sLoSum, 2);
            sHiSum += __shfl_xor_sync(0xffffffffu, sHiSum, 1);
            sHiSum += __shfl_xor_sync(0xffffffffu, sHiSum, 2);
            lLo = lLo * aLo + sLoSum;
            lHi = lHi * aHi + sHiSum;
            // Rescale O
            #pragma unroll
            for (int nb = 0; nb < 16; nb++) {
                O[nb][0] *= aLo; O[nb][1] *= aLo;
                O[nb][2] *= aHi; O[nb][3] *= aHi;
            }
        }
        __syncwarp();   // Ps strip is warp-private; make lane writes visible

        // V(mt) ready (pending: {V(mt), K(mt+1)}; last iter: {V(mt)})
        if (mt < mtMax) {
            asm volatile("cp.async.wait_group 1;" ::: "memory");
        } else {
            asm volatile("cp.async.wait_group 0;" ::: "memory");
        }
        __syncthreads();

        // ---- O += P @ V^T : warp tile 16 rows x 128 v-channels (nf=16) ----
        #pragma unroll
        for (int kf = 0; kf < 8; kf++) {
            int kc = kf * 8;
            int ab = (wq + lr) * SP + kc + lc;
            uint32_t a0 = __float_as_uint(Ps[ab]);
            uint32_t a1 = __float_as_uint(Ps[ab + 8 * SP]);   // row+8
            uint32_t a2 = __float_as_uint(Ps[ab + 4]);        // k+4
            uint32_t a3 = __float_as_uint(Ps[ab + 8 * SP + 4]);
            #pragma unroll
            for (int nb = 0; nb < 16; nb++) {
                int bb = (nb * 8 + lr) * SV + kc + lc;
                uint32_t b0 = __float_as_uint(Vs[bb]);
                uint32_t b1 = __float_as_uint(Vs[bb + 4]);    // k+4
                mma_tf32(O[nb][0], O[nb][1], O[nb][2], O[nb][3], a0, a1, a2, a3, b0, b1);
            }
        }
        __syncthreads();                  // all warps done reading Vs
        if (mt < mtMax) issue_v(mt + 1);  // hidden behind next S phase
    }

    // Normalize and store
    float iLo = 1.0f / lLo, iHi = 1.0f / lHi;
    #pragma unroll
    for (int nb = 0; nb < 16; nb++) {
        int vc = nb * 8 + 2 * lc;
        out[((size_t)(b * 128 + vc))     * 1024 + rowLo] = O[nb][0] * iLo;
        out[((size_t)(b * 128 + vc + 1)) * 1024 + rowLo] = O[nb][1] * iLo;
        out[((size_t)(b * 128 + vc))     * 1024 + rowHi] = O[nb][2] * iHi;
        out[((size_t)(b * 128 + vc + 1)) * 1024 + rowHi] = O[nb][3] * iHi;
    }
}

// ---------------------------------------------------------------------------
// Launch (single stream, graph-capturable)
// ---------------------------------------------------------------------------
extern "C" void kernel_launch(void* const* d_in, const int* in_sizes, int n_in,
                              void* d_out, int out_size)
{
    const float* x   = (const float*)d_in[0];
    const float* k   = (const float*)d_in[1];
    const float* v   = (const float*)d_in[2];
    const float* Wq  = (const float*)d_in[3];
    const float* bq  = (const float*)d_in[4];
    const float* Wfk = (const float*)d_in[5];
    const float* bfk = (const float*)d_in[6];
    const float* Wck = (const float*)d_in[7];
    const float* bck = (const float*)d_in[8];
    const float* Wfv = (const float*)d_in[9];
    const float* bfv = (const float*)d_in[10];
    const float* Wcv = (const float*)d_in[11];
    const float* bcv = (const float*)d_in[12];

    float* out2 = (float*)d_out;
    float* kn   = out2 + (size_t)32 * 128 * 1024;
    float* vn   = kn   + (size_t)32 * 128 * 1024;

    cudaFuncSetAttribute(fused_gemm_kernel, cudaFuncAttributeMaxDynamicSharedMemorySize, GSMEM_BYTES);
    cudaFuncSetAttribute(attn_kernel, cudaFuncAttributeMaxDynamicSharedMemorySize, ATTN_SMEM_BYTES);

    pos_kernel<<<32, 1024>>>();
    pack_kernel<<<(PACK_TOTAL + 255) / 256, 256>>>(x, k, v, Wq, Wfk, Wck, Wfv, Wcv);
    fused_gemm_kernel<<<dim3(8, 2, 96), 256, GSMEM_BYTES>>>(
        k, v, bfk, bck, bfv, bcv, bq, kn, vn);
    attn_kernel<<<dim3(8, 32), 256, ATTN_SMEM_BYTES>>>(out2);
}

// round 8
// speedup vs baseline: 1.1359x; 1.0148x over previous
#include <cuda_runtime.h>
#include <math.h>
#include <stdint.h>

// ---------------------------------------------------------------------------
// Scratch (__device__ globals; no allocation allowed)
// ---------------------------------------------------------------------------
__device__ float g_pos[32 * 1024];              // [32 ch][1024], fp32
__device__ float g_x0[32 * 160 * 1024];         // tf32 [B][160][N]  (x|pos)
__device__ float g_kc[32 * 128 * 1024];         // tf32 k
__device__ float g_vc[32 * 128 * 1024];         // tf32 v
__device__ float g_q [32 * 128 * 1024];         // tf32 q
__device__ float g_Wq [128 * 160];              // tf32 weights
__device__ float g_Wfk[128 * 288];
__device__ float g_Wck[128 * 288];
__device__ float g_Wfv[128 * 288];
__device__ float g_Wcv[128 * 288];

// ---------------------------------------------------------------------------
// Helpers
// ---------------------------------------------------------------------------
__device__ __forceinline__ uint32_t f2tf(float x) {
    uint32_t u;
    asm("cvt.rna.tf32.f32 %0, %1;" : "=r"(u) : "f"(x));
    return u;
}
__device__ __forceinline__ float f2tff(float x) { return __uint_as_float(f2tf(x)); }

__device__ __forceinline__ void mma_tf32(
    float& d0, float& d1, float& d2, float& d3,
    uint32_t a0, uint32_t a1, uint32_t a2, uint32_t a3,
    uint32_t b0, uint32_t b1)
{
    asm volatile(
        "mma.sync.aligned.m16n8k8.row.col.f32.tf32.tf32.f32 "
        "{%0,%1,%2,%3}, {%4,%5,%6,%7}, {%8,%9}, {%0,%1,%2,%3};"
        : "+f"(d0), "+f"(d1), "+f"(d2), "+f"(d3)
        : "r"(a0), "r"(a1), "r"(a2), "r"(a3), "r"(b0), "r"(b1));
}

__device__ __forceinline__ void cpa16(uint32_t dst, const void* src) {
    asm volatile("cp.async.ca.shared.global [%0], [%1], 16;" :: "r"(dst), "l"(src));
}
#define CP_COMMIT() asm volatile("cp.async.commit_group;" ::: "memory")

// ---------------------------------------------------------------------------
// Positional embedding (faithful to numpy .view reinterpret)
// ---------------------------------------------------------------------------
__global__ void pos_kernel() {
    int idx = blockIdx.x * blockDim.x + threadIdx.x;
    if (idx >= 32 * 1024) return;
    int c = idx >> 10, n = idx & 1023;
    int y = n >> 5, x = n & 31;
    int i = (c < 16) ? (c * 32 + y) : ((c - 16) * 32 + x);
    int p = i >> 4, j = i & 15;
    float r = 0.0f;
    if (p != 0) {
        double denom = pow(10000.0, (double)(2 * (j >> 1)) / 16.0);
        double val = (double)p / denom;
        r = (j & 1) ? (float)cos(val) : (float)sin(val);
    }
    g_pos[idx] = r;
}

// ---------------------------------------------------------------------------
// Pack: tf32-round inputs AND weights into scratch (one launch)
// ---------------------------------------------------------------------------
__device__ __forceinline__ float4 tf4(float4 s) {
    s.x = f2tff(s.x); s.y = f2tff(s.y); s.z = f2tff(s.z); s.w = f2tff(s.w);
    return s;
}

#define PACK_NX0 (32 * 160 * 256)
#define PACK_NKV (32 * 128 * 256)
#define PACK_DATA (PACK_NX0 + 2 * PACK_NKV)
#define PACK_TOTAL (PACK_DATA + 128 * 288)

__global__ void pack_kernel(const float* __restrict__ x,
                            const float* __restrict__ k,
                            const float* __restrict__ v,
                            const float* __restrict__ Wq,
                            const float* __restrict__ Wfk, const float* __restrict__ Wck,
                            const float* __restrict__ Wfv, const float* __restrict__ Wcv)
{
    int i = blockIdx.x * blockDim.x + threadIdx.x;
    if (i < PACK_NX0) {
        int n4 = i & 255;
        int cb = i >> 8;
        int c = cb % 160, b = cb / 160;
        float4 s;
        if (c < 128)
            s = ((const float4*)x)[(size_t)(b * 128 + c) * 256 + n4];
        else
            s = ((const float4*)g_pos)[(c - 128) * 256 + n4];
        ((float4*)g_x0)[i] = tf4(s);
    } else if (i < PACK_NX0 + PACK_NKV) {
        int j = i - PACK_NX0;
        ((float4*)g_kc)[j] = tf4(((const float4*)k)[j]);
    } else if (i < PACK_DATA) {
        int j = i - PACK_NX0 - PACK_NKV;
        ((float4*)g_vc)[j] = tf4(((const float4*)v)[j]);
    } else {
        int j = i - PACK_DATA;                 // 0 .. 128*288-1
        if (j < 128 * 160) g_Wq[j] = f2tff(Wq[j]);
        g_Wfk[j] = f2tff(Wfk[j]);
        g_Wck[j] = f2tff(Wck[j]);
        g_Wfv[j] = f2tff(Wfv[j]);
        g_Wcv[j] = f2tff(Wcv[j]);
    }
}

// ---------------------------------------------------------------------------
// Fused GEMM kernel (unchanged, proven):
//   z in [0,64)  : gated highway update (z = b*2 + which), K=288, 9 steps
//   z in [64,96) : q = tf32(relu(Wq@x0+bq)) for b = z-64, K=160, 5 steps
// ---------------------------------------------------------------------------
#define GSA 36          // A smem row stride (words); 36 % 32 == 4
#define GSB 136         // B smem row stride; 136 % 32 == 8
#define GBUF 8960       // floats per gated pipeline buffer (2*64*GSA + 32*GSB)
#define GSMEM_BYTES (2 * GBUF * 4)
#define QBUF 6656       // floats per q pipeline buffer (64*GSA + 32*GSB)

__global__ __launch_bounds__(256, 2) void fused_gemm_kernel(
    const float* __restrict__ kOrig, const float* __restrict__ vOrig,
    const float* __restrict__ bfk, const float* __restrict__ bck,
    const float* __restrict__ bfv, const float* __restrict__ bcv,
    const float* __restrict__ bq,
    float* __restrict__ outk, float* __restrict__ outv)
{
    extern __shared__ float sm[];
    const int r0 = blockIdx.y * 64, n0 = blockIdx.x * 128;
    const int t = threadIdx.x, w = t >> 5, lane = t & 31;
    const int lr = lane >> 2, lc = lane & 3;
    const int wm = (w >> 2) * 32;   // 0 / 32
    const int wn = (w & 3) * 32;    // 0,32,64,96
    const uint32_t sbase = (uint32_t)__cvta_generic_to_shared(sm);

    if (blockIdx.z < 64) {
        // ================= gated body =================
        const int z = blockIdx.z, b = z >> 1, which = z & 1;
        const float* Wf   = which ? g_Wfv : g_Wfk;
        const float* Wc   = which ? g_Wcv : g_Wck;
        const float* bfp  = which ? bfv : bfk;
        const float* bcp  = which ? bcv : bck;
        const float* extc = which ? g_vc : g_kc;
        const float* extra = which ? vOrig : kOrig;
        float* out = which ? outv : outk;

        float accF[2][4][4], accC[2][4][4];
        #pragma unroll
        for (int mf = 0; mf < 2; mf++) {
            int rA = r0 + wm + mf * 16 + lr;
            float bf0 = bfp[rA], bf1 = bfp[rA + 8];
            float bc0 = bcp[rA], bc1 = bcp[rA + 8];
            #pragma unroll
            for (int nf = 0; nf < 4; nf++) {
                accF[mf][nf][0] = bf0; accF[mf][nf][1] = bf0;
                accF[mf][nf][2] = bf1; accF[mf][nf][3] = bf1;
                accC[mf][nf][0] = bc0; accC[mf][nf][1] = bc0;
                accC[mf][nf][2] = bc1; accC[mf][nf][3] = bc1;
            }
        }

        auto issue = [&](int it, int buf) {
            const int k0 = it * 32;
            const uint32_t base = sbase + buf * (GBUF * 4);
            #pragma unroll
            for (int h = 0; h < 2; h++) {
                int a = t + 256 * h;                // 0..511
                int r = a >> 3, c4 = a & 7;
                cpa16(base + (r * GSA + c4 * 4) * 4,
                      Wf + (size_t)(r0 + r) * 288 + k0 + c4 * 4);
                cpa16(base + (2304 + r * GSA + c4 * 4) * 4,
                      Wc + (size_t)(r0 + r) * 288 + k0 + c4 * 4);
            }
            #pragma unroll
            for (int h = 0; h < 4; h++) {
                int bi = t + 256 * h;               // 0..1023
                int r = bi >> 5, c4 = bi & 31;
                int row = k0 + r;
                const float* src = (row < 160)
                    ? (g_x0 + ((size_t)b * 160 + row) * 1024 + n0 + c4 * 4)
                    : (extc + ((size_t)b * 128 + (row - 160)) * 1024 + n0 + c4 * 4);
                cpa16(base + (4608 + r * GSB + c4 * 4) * 4, src);
            }
            CP_COMMIT();
        };

        issue(0, 0);
        #pragma unroll 1
        for (int it = 0; it < 9; it++) {
            if (it < 8) {
                issue(it + 1, (it + 1) & 1);
                asm volatile("cp.async.wait_group 1;" ::: "memory");
            } else {
                asm volatile("cp.async.wait_group 0;" ::: "memory");
            }
            __syncthreads();

            const float* AsF = sm + (it & 1) * GBUF;
            const float* AsC = AsF + 2304;
            const float* Bs  = AsF + 4608;

            #pragma unroll
            for (int kf = 0; kf < 4; kf++) {
                int kk = kf * 8;
                uint32_t aF[2][4], aC[2][4], bb[4][2];
                #pragma unroll
                for (int mf = 0; mf < 2; mf++) {
                    int base = (wm + mf * 16 + lr) * GSA + kk + lc;
                    aF[mf][0] = __float_as_uint(AsF[base]);
                    aF[mf][1] = __float_as_uint(AsF[base + 8 * GSA]);
                    aF[mf][2] = __float_as_uint(AsF[base + 4]);
                    aF[mf][3] = __float_as_uint(AsF[base + 8 * GSA + 4]);
                    aC[mf][0] = __float_as_uint(AsC[base]);
                    aC[mf][1] = __float_as_uint(AsC[base + 8 * GSA]);
                    aC[mf][2] = __float_as_uint(AsC[base + 4]);
                    aC[mf][3] = __float_as_uint(AsC[base + 8 * GSA + 4]);
                }
                #pragma unroll
                for (int nf = 0; nf < 4; nf++) {
                    int base = (kk + lc) * GSB + wn + nf * 8 + lr;
                    bb[nf][0] = __float_as_uint(Bs[base]);
                    bb[nf][1] = __float_as_uint(Bs[base + 4 * GSB]);
                }
                #pragma unroll
                for (int mf = 0; mf < 2; mf++)
                    #pragma unroll
                    for (int nf = 0; nf < 4; nf++) {
                        mma_tf32(accF[mf][nf][0], accF[mf][nf][1], accF[mf][nf][2], accF[mf][nf][3],
                                 aF[mf][0], aF[mf][1], aF[mf][2], aF[mf][3], bb[nf][0], bb[nf][1]);
                        mma_tf32(accC[mf][nf][0], accC[mf][nf][1], accC[mf][nf][2], accC[mf][nf][3],
                                 aC[mf][0], aC[mf][1], aC[mf][2], aC[mf][3], bb[nf][0], bb[nf][1]);
                    }
            }
            __syncthreads();
        }

        #pragma unroll
        for (int mf = 0; mf < 2; mf++) {
            int rA = r0 + wm + mf * 16 + lr;
            #pragma unroll
            for (int nf = 0; nf < 4; nf++) {
                int n = n0 + wn + nf * 8 + 2 * lc;
                #pragma unroll
                for (int h = 0; h < 2; h++) {
                    int row = rA + h * 8;
                    #pragma unroll
                    for (int j = 0; j < 2; j++) {
                        float F  = accF[mf][nf][2 * h + j];
                        float Cc = accC[mf][nf][2 * h + j];
                        float f  = 1.0f / (1.0f + __expf(-F));
                        float cc = fmaxf(Cc, 0.0f);
                        size_t off = ((size_t)(b * 128 + row)) * 1024 + n + j;
                        out[off] = f * extra[off] + cc;
                    }
                }
            }
        }
    } else {
        // ================= q body =================
        const int b = blockIdx.z - 64;

        float acc[2][4][4];
        #pragma unroll
        for (int mf = 0; mf < 2; mf++) {
            int rA = r0 + wm + mf * 16 + lr;
            float b0 = bq[rA], b1 = bq[rA + 8];
            #pragma unroll
            for (int nf = 0; nf < 4; nf++) {
                acc[mf][nf][0] = b0; acc[mf][nf][1] = b0;
                acc[mf][nf][2] = b1; acc[mf][nf][3] = b1;
            }
        }

        auto issue = [&](int it, int buf) {
            const int k0 = it * 32;
            const uint32_t base = sbase + buf * (QBUF * 4);
            #pragma unroll
            for (int h = 0; h < 2; h++) {
                int a = t + 256 * h;
                int r = a >> 3, c4 = a & 7;
                cpa16(base + (r * GSA + c4 * 4) * 4,
                      g_Wq + (size_t)(r0 + r) * 160 + k0 + c4 * 4);
            }
            #pragma unroll
            for (int h = 0; h < 4; h++) {
                int bi = t + 256 * h;
                int r = bi >> 5, c4 = bi & 31;
                cpa16(base + (2304 + r * GSB + c4 * 4) * 4,
                      g_x0 + ((size_t)b * 160 + k0 + r) * 1024 + n0 + c4 * 4);
            }
            CP_COMMIT();
        };

        issue(0, 0);
        #pragma unroll 1
        for (int it = 0; it < 5; it++) {
            if (it < 4) {
                issue(it + 1, (it + 1) & 1);
                asm volatile("cp.async.wait_group 1;" ::: "memory");
            } else {
                asm volatile("cp.async.wait_group 0;" ::: "memory");
            }
            __syncthreads();

            const float* As = sm + (it & 1) * QBUF;
            const float* Bs = As + 2304;

            #pragma unroll
            for (int kf = 0; kf < 4; kf++) {
                int kk = kf * 8;
                uint32_t aa[2][4], bb[4][2];
                #pragma unroll
                for (int mf = 0; mf < 2; mf++) {
                    int base = (wm + mf * 16 + lr) * GSA + kk + lc;
                    aa[mf][0] = __float_as_uint(As[base]);
                    aa[mf][1] = __float_as_uint(As[base + 8 * GSA]);
                    aa[mf][2] = __float_as_uint(As[base + 4]);
                    aa[mf][3] = __float_as_uint(As[base + 8 * GSA + 4]);
                }
                #pragma unroll
                for (int nf = 0; nf < 4; nf++) {
                    int base = (kk + lc) * GSB + wn + nf * 8 + lr;
                    bb[nf][0] = __float_as_uint(Bs[base]);
                    bb[nf][1] = __float_as_uint(Bs[base + 4 * GSB]);
                }
                #pragma unroll
                for (int mf = 0; mf < 2; mf++)
                    #pragma unroll
                    for (int nf = 0; nf < 4; nf++)
                        mma_tf32(acc[mf][nf][0], acc[mf][nf][1], acc[mf][nf][2], acc[mf][nf][3],
                                 aa[mf][0], aa[mf][1], aa[mf][2], aa[mf][3], bb[nf][0], bb[nf][1]);
            }
            __syncthreads();
        }

        #pragma unroll
        for (int mf = 0; mf < 2; mf++) {
            int rA = r0 + wm + mf * 16 + lr;
            #pragma unroll
            for (int nf = 0; nf < 4; nf++) {
                int n = n0 + wn + nf * 8 + 2 * lc;
                #pragma unroll
                for (int h = 0; h < 2; h++) {
                    int row = rA + h * 8;
                    #pragma unroll
                    for (int j = 0; j < 2; j++) {
                        float val = fmaxf(acc[mf][nf][2 * h + j], 0.0f);
                        g_q[((size_t)(b * 128 + row)) * 1024 + n + j] = f2tff(val);
                    }
                }
            }
        }
    }
}

// ---------------------------------------------------------------------------
// Causal attention, FA2-style, Round 8:
//   - Q fragments fully register-resident (loaded once from g_q; no Qs smem)
//   - K and V double-buffered in smem; ONE __syncthreads per kv-iteration
//   - warp-owned 16 q-rows x 64 keys (S) / x 128 v-channels (PV)
//   - softmax stats in registers; P in warp-private smem strip (__syncwarp)
// smem = 2*Ks + 2*Vs + Ps = 178.2 KB, 1 CTA/SM, 8 warps.
// ---------------------------------------------------------------------------
#define SK  72    // Ks stride: 64 keys + 8 pad
#define SV  68    // Vs stride: 64 keys + 4 pad
#define SP  68    // Ps stride: 64 keys + 4 pad
#define KS_FL (128 * SK)                  // 9216
#define VS_FL (128 * SV)                  // 8704

#define OFF_KS0 0
#define OFF_KS1 KS_FL
#define OFF_VS0 (2 * KS_FL)
#define OFF_VS1 (2 * KS_FL + VS_FL)
#define OFF_PS  (2 * KS_FL + 2 * VS_FL)   // 35840
#define ATTN_SMEM_FLOATS (OFF_PS + 128 * SP)    // 44544
#define ATTN_SMEM_BYTES (ATTN_SMEM_FLOATS * 4)  // 178176

__global__ __launch_bounds__(256, 1) void attn_kernel(float* __restrict__ out)
{
    extern __shared__ float sm[];
    float* Ps = sm + OFF_PS;

    const int b = blockIdx.y;
    const int qt = 7 - blockIdx.x;        // heavy q-tiles first
    const int n0 = qt * 128;
    const int mtMax = 2 * qt + 1;
    const int t = threadIdx.x, w = t >> 5, lane = t & 31;
    const int lr = lane >> 2, lc = lane & 3;
    const int wq = w * 16;                // warp's local q-row base
    const float scale = 0.08838834764831845f;
    const uint32_t sbase = (uint32_t)__cvta_generic_to_shared(sm);

    // One commit group per stage: K(mt) + V(mt) into buffer mt&1
    auto issue_stage = [&](int mt) {
        const int p = mt & 1;
        const int m0 = mt * 64;
        const uint32_t kb = sbase + (p ? OFF_KS1 : OFF_KS0) * 4;
        const uint32_t vb = sbase + (p ? OFF_VS1 : OFF_VS0) * 4;
        #pragma unroll
        for (int h = 0; h < 8; h++) {
            int idx = t + 256 * h;            // 0..2047
            int c = idx >> 4, m4 = idx & 15;
            cpa16(kb + (c * SK + m4 * 4) * 4,
                  g_kc + ((size_t)(b * 128 + c)) * 1024 + m0 + m4 * 4);
            cpa16(vb + (c * SV + m4 * 4) * 4,
                  g_vc + ((size_t)(b * 128 + c)) * 1024 + m0 + m4 * 4);
        }
        CP_COMMIT();
    };

    issue_stage(0);

    // Q fragments register-resident: qa[kf] covers k=kf*8..+7 for this warp's
    // 16 rows. a0=Q[row][k], a1=Q[row+8][k], a2=Q[row][k+4], a3=Q[row+8][k+4],
    // where Q[n][c] = g_q[(b*128+c)*1024 + n].  (overlaps stage-0 cp.async)
    uint32_t qa[16][4];
    #pragma unroll
    for (int kf = 0; kf < 16; kf++) {
        const float* qp = g_q + ((size_t)(b * 128 + kf * 8 + lc)) * 1024 + n0 + wq + lr;
        qa[kf][0] = __float_as_uint(qp[0]);
        qa[kf][1] = __float_as_uint(qp[8]);
        qa[kf][2] = __float_as_uint(qp[4 * 1024]);
        qa[kf][3] = __float_as_uint(qp[4 * 1024 + 8]);
    }

    // Running stats (registers; rows wq+lr and wq+lr+8)
    float mLo = -1e30f, mHi = -1e30f, lLo = 0.0f, lHi = 0.0f;
    float O[16][4];
    #pragma unroll
    for (int nb = 0; nb < 16; nb++)
        #pragma unroll
        for (int j = 0; j < 4; j++) O[nb][j] = 0.0f;

    const int rowLo = n0 + wq + lr;
    const int rowHi = rowLo + 8;

    #pragma unroll 1
    for (int mt = 0; mt <= mtMax; mt++) {
        const int m0 = mt * 64;
        const float* Ks = sm + ((mt & 1) ? OFF_KS1 : OFF_KS0);
        const float* Vs = sm + ((mt & 1) ? OFF_VS1 : OFF_VS0);

        // Stage mt arrived (only pending group); barrier doubles as
        // "all warps done reading buffer (mt+1)&1 in iter mt-1".
        asm volatile("cp.async.wait_group 0;" ::: "memory");
        __syncthreads();
        if (mt < mtMax) issue_stage(mt + 1);   // hidden behind S+softmax+PV

        // ---- S = Q^T K : warp tile 16 x 64 (A from registers) ----
        float S[8][4];
        #pragma unroll
        for (int nb = 0; nb < 8; nb++)
            #pragma unroll
            for (int j = 0; j < 4; j++) S[nb][j] = 0.0f;

        #pragma unroll
        for (int kf = 0; kf < 16; kf++) {
            int kc = kf * 8;
            #pragma unroll
            for (int nb = 0; nb < 8; nb++) {
                int bbase = (kc + lc) * SK + nb * 8 + lr;
                uint32_t b0 = __float_as_uint(Ks[bbase]);
                uint32_t b1 = __float_as_uint(Ks[bbase + 4 * SK]);
                mma_tf32(S[nb][0], S[nb][1], S[nb][2], S[nb][3],
                         qa[kf][0], qa[kf][1], qa[kf][2], qa[kf][3], b0, b1);
            }
        }

        // ---- In-register online softmax (warp-local, no CTA barrier) ----
        {
            const bool needMask = (m0 + 63 > n0 + wq);
            float tmLo = -1e30f, tmHi = -1e30f;
            #pragma unroll
            for (int nb = 0; nb < 8; nb++) {
                int c0 = m0 + nb * 8 + 2 * lc, c1 = c0 + 1;
                float s0 = S[nb][0] * scale, s1 = S[nb][1] * scale;
                float s2 = S[nb][2] * scale, s3 = S[nb][3] * scale;
                if (needMask) {
                    if (c0 > rowLo) s0 = -1e30f;
                    if (c1 > rowLo) s1 = -1e30f;
                    if (c0 > rowHi) s2 = -1e30f;
                    if (c1 > rowHi) s3 = -1e30f;
                }
                S[nb][0] = s0; S[nb][1] = s1; S[nb][2] = s2; S[nb][3] = s3;
                tmLo = fmaxf(tmLo, fmaxf(s0, s1));
                tmHi = fmaxf(tmHi, fmaxf(s2, s3));
            }
            tmLo = fmaxf(tmLo, __shfl_xor_sync(0xffffffffu, tmLo, 1));
            tmLo = fmaxf(tmLo, __shfl_xor_sync(0xffffffffu, tmLo, 2));
            tmHi = fmaxf(tmHi, __shfl_xor_sync(0xffffffffu, tmHi, 1));
            tmHi = fmaxf(tmHi, __shfl_xor_sync(0xffffffffu, tmHi, 2));
            float nmLo = fmaxf(mLo, tmLo), nmHi = fmaxf(mHi, tmHi);
            float aLo = __expf(mLo - nmLo), aHi = __expf(mHi - nmHi);
            mLo = nmLo; mHi = nmHi;
            float sLoSum = 0.0f, sHiSum = 0.0f;
            #pragma unroll
            for (int nb = 0; nb < 8; nb++) {
                float p0 = f2tff(__expf(S[nb][0] - nmLo));
                float p1 = f2tff(__expf(S[nb][1] - nmLo));
                float p2 = f2tff(__expf(S[nb][2] - nmHi));
                float p3 = f2tff(__expf(S[nb][3] - nmHi));
                sLoSum += p0 + p1;
                sHiSum += p2 + p3;
                int pb = (wq + lr) * SP + nb * 8 + 2 * lc;
                *(float2*)&Ps[pb]          = make_float2(p0, p1);
                *(float2*)&Ps[pb + 8 * SP] = make_float2(p2, p3);
            }
            sLoSum += __shfl_xor_sync(0xffffffffu, sLoSum, 1);
            sLoSum += __shfl_xor_sync(0xffffffffu, sLoSum, 2);
            sHiSum += __shfl_xor_sync(0xffffffffu, sHiSum, 1);
            sHiSum += __shfl_xor_sync(0xffffffffu, sHiSum, 2);
            lLo = lLo * aLo + sLoSum;
            lHi = lHi * aHi + sHiSum;
            #pragma unroll
            for (int nb = 0; nb < 16; nb++) {
                O[nb][0] *= aLo; O[nb][1] *= aLo;
                O[nb][2] *= aHi; O[nb][3] *= aHi;
            }
        }
        __syncwarp();   // Ps strip is warp-private; make lane writes visible

        // ---- O += P @ V^T : warp tile 16 rows x 128 v-channels ----
        #pragma unroll
        for (int kf = 0; kf < 8; kf++) {
            int kc = kf * 8;
            int ab = (wq + lr) * SP + kc + lc;
            uint32_t a0 = __float_as_uint(Ps[ab]);
            uint32_t a1 = __float_as_uint(Ps[ab + 8 * SP]);   // row+8
            uint32_t a2 = __float_as_uint(Ps[ab + 4]);        // k+4
            uint32_t a3 = __float_as_uint(Ps[ab + 8 * SP + 4]);
            #pragma unroll
            for (int nb = 0; nb < 16; nb++) {
                int bb = (nb * 8 + lr) * SV + kc + lc;
                uint32_t b0 = __float_as_uint(Vs[bb]);
                uint32_t b1 = __float_as_uint(Vs[bb + 4]);    // k+4
                mma_tf32(O[nb][0], O[nb][1], O[nb][2], O[nb][3], a0, a1, a2, a3, b0, b1);
            }
        }
        // no end-of-iter barrier: next iteration's top barrier protects reuse
    }

    // Normalize and store
    float iLo = 1.0f / lLo, iHi = 1.0f / lHi;
    #pragma unroll
    for (int nb = 0; nb < 16; nb++) {
        int vc = nb * 8 + 2 * lc;
        out[((size_t)(b * 128 + vc))     * 1024 + rowLo] = O[nb][0] * iLo;
        out[((size_t)(b * 128 + vc + 1)) * 1024 + rowLo] = O[nb][1] * iLo;
        out[((size_t)(b * 128 + vc))     * 1024 + rowHi] = O[nb][2] * iHi;
        out[((size_t)(b * 128 + vc + 1)) * 1024 + rowHi] = O[nb][3] * iHi;
    }
}

// ---------------------------------------------------------------------------
// Launch (single stream, graph-capturable)
// ---------------------------------------------------------------------------
extern "C" void kernel_launch(void* const* d_in, const int* in_sizes, int n_in,
                              void* d_out, int out_size)
{
    const float* x   = (const float*)d_in[0];
    const float* k   = (const float*)d_in[1];
    const float* v   = (const float*)d_in[2];
    const float* Wq  = (const float*)d_in[3];
    const float* bq  = (const float*)d_in[4];
    const float* Wfk = (const float*)d_in[5];
    const float* bfk = (const float*)d_in[6];
    const float* Wck = (const float*)d_in[7];
    const float* bck = (const float*)d_in[8];
    const float* Wfv = (const float*)d_in[9];
    const float* bfv = (const float*)d_in[10];
    const float* Wcv = (const float*)d_in[11];
    const float* bcv = (const float*)d_in[12];

    float* out2 = (float*)d_out;
    float* kn   = out2 + (size_t)32 * 128 * 1024;
    float* vn   = kn   + (size_t)32 * 128 * 1024;

    cudaFuncSetAttribute(fused_gemm_kernel, cudaFuncAttributeMaxDynamicSharedMemorySize, GSMEM_BYTES);
    cudaFuncSetAttribute(attn_kernel, cudaFuncAttributeMaxDynamicSharedMemorySize, ATTN_SMEM_BYTES);

    pos_kernel<<<32, 1024>>>();
    pack_kernel<<<(PACK_TOTAL + 255) / 256, 256>>>(x, k, v, Wq, Wfk, Wck, Wfv, Wcv);
    fused_gemm_kernel<<<dim3(8, 2, 96), 256, GSMEM_BYTES>>>(
        k, v, bfk, bck, bfv, bcv, bq, kn, vn);
    attn_kernel<<<dim3(8, 32), 256, ATTN_SMEM_BYTES>>>(out2);
}